// round 5
// baseline (speedup 1.0000x reference)
#include <cuda_runtime.h>
#include <cstdint>

// ---------------- problem constants ----------------
#define B_    2
#define S_    4096
#define H_    16
#define NBLK  255
#define R_    512
#define ROPE_ 64
#define QKD_  192
#define VD_   128
#define KER_  32
#define STR_  16
#define TOPK_ 16
#define SCALE_ 0.07216878364870323f

#define KSPLIT 8

// ---------------- scratch (device globals; no cudaMalloc allowed) ----------
__device__ float g_scr_kv[KSPLIT * 512 * 512];   // split-K partials for cmp_kv
__device__ float g_scr_pe[KSPLIT * 512 * 64];    // split-K partials for cmp_pe
__device__ float g_cmp_kv[510 * 512];
__device__ float g_cmp_pe[510 * 64];
__device__ float g_Kf[(size_t)B_ * H_ * NBLK * QKD_];  // per-head K (nope||rope)
__device__ float g_Vf[(size_t)B_ * H_ * NBLK * VD_];   // per-head V
__device__ float g_pagg[(size_t)B_ * S_ * 256];        // max-over-heads probs (padded nblk->256)

// ---------------- zero p_agg ----------------
__global__ void zero_pagg_kernel() {
    size_t i = (size_t)blockIdx.x * blockDim.x + threadIdx.x;
    size_t n = (size_t)B_ * S_ * 256;
    if (i < n) g_pagg[i] = 0.f;
}

// ---------------- gathered split-K GEMM ----------------
// scratch[z][m][n] = sum_{k in chunk z} A[m][k] * W[k][n]
// A[m][k] = src[b][ n_blk*16 + (k>>logF) ][ k & (F-1) ],  m=(b,n_blk), b=m/255
// mode 0: cmp_kv (F=512, N=512) -> g_scr_kv ; mode 1: cmp_pe (F=64, N=64) -> g_scr_pe
__global__ void gather_gemm_kernel(const float* __restrict__ src,
                                   const float* __restrict__ W,
                                   int logF, int N, int KC, int mode)
{
    __shared__ float sA[16 * 65];
    __shared__ float sB[16 * 64];
    float* scratch = mode ? g_scr_pe : g_scr_kv;
    const int F = 1 << logF;
    const int m0 = blockIdx.x * 64, n0 = blockIdx.y * 64;
    const int k0 = blockIdx.z * KC;
    const int t = threadIdx.x;
    const int ty = t >> 4, tx = t & 15;

    float acc[4][4];
#pragma unroll
    for (int i = 0; i < 4; i++)
#pragma unroll
        for (int j = 0; j < 4; j++) acc[i][j] = 0.f;

    for (int ks = 0; ks < KC; ks += 16) {
#pragma unroll
        for (int i = 0; i < 4; i++) {
            int idx = t + i * 256;
            int mm = idx >> 4, kk = idx & 15;
            int m = m0 + mm;
            float v = 0.f;
            if (m < 510) {
                int bb = (m >= NBLK) ? 1 : 0;
                int nb = m - bb * NBLK;
                int k = k0 + ks + kk;
                int p = k >> logF, c = k & (F - 1);
                v = src[(((size_t)bb * S_ + nb * STR_ + p) << logF) + c];
            }
            sA[kk * 65 + mm] = v;
        }
#pragma unroll
        for (int i = 0; i < 4; i++) {
            int idx = t + i * 256;
            int kk = idx >> 6, nn = idx & 63;
            sB[kk * 64 + nn] = W[(size_t)(k0 + ks + kk) * N + n0 + nn];
        }
        __syncthreads();
#pragma unroll
        for (int kk = 0; kk < 16; kk++) {
            float a[4], bv[4];
#pragma unroll
            for (int i = 0; i < 4; i++) a[i] = sA[kk * 65 + ty + 16 * i];
#pragma unroll
            for (int j = 0; j < 4; j++) bv[j] = sB[kk * 64 + tx + 16 * j];
#pragma unroll
            for (int i = 0; i < 4; i++)
#pragma unroll
                for (int j = 0; j < 4; j++) acc[i][j] += a[i] * bv[j];
        }
        __syncthreads();
    }
#pragma unroll
    for (int i = 0; i < 4; i++)
#pragma unroll
        for (int j = 0; j < 4; j++)
            scratch[((size_t)blockIdx.z * 512 + m0 + ty + 16 * i) * N + n0 + tx + 16 * j] = acc[i][j];
}

// ---------------- split-K reduction ----------------
__global__ void reduce_kernel() {
    int i = blockIdx.x * blockDim.x + threadIdx.x;
    if (i < 510 * 512) {
        int m = i / 512, n = i % 512;
        float s = 0.f;
#pragma unroll
        for (int kc = 0; kc < KSPLIT; kc++) s += g_scr_kv[((size_t)kc * 512 + m) * 512 + n];
        g_cmp_kv[i] = s;
    } else if (i < 510 * 512 + 510 * 64) {
        int j = i - 510 * 512;
        int m = j / 64, e = j % 64;
        float s = 0.f;
#pragma unroll
        for (int kc = 0; kc < KSPLIT; kc++) s += g_scr_pe[((size_t)kc * 512 + m) * 64 + e];
        g_cmp_pe[j] = s;
    }
}

// ---------------- kvb GEMM with scatter into Kf/Vf ----------------
// kvb[m][nn] = cmp_kv[m][:] . W_kv_b[:][nn];  nn = h*256 + d; d<128 -> K nope, else V
__global__ void kvb_gemm_kernel(const float* __restrict__ Wkb)
{
    __shared__ float sA[16 * 65];
    __shared__ float sB[16 * 64];
    const int m0 = blockIdx.x * 64, n0 = blockIdx.y * 64;
    const int t = threadIdx.x;
    const int ty = t >> 4, tx = t & 15;

    float acc[4][4];
#pragma unroll
    for (int i = 0; i < 4; i++)
#pragma unroll
        for (int j = 0; j < 4; j++) acc[i][j] = 0.f;

    for (int ks = 0; ks < 512; ks += 16) {
#pragma unroll
        for (int i = 0; i < 4; i++) {
            int idx = t + i * 256;
            int mm = idx >> 4, kk = idx & 15;
            int m = m0 + mm;
            sA[kk * 65 + mm] = (m < 510) ? g_cmp_kv[(size_t)m * 512 + ks + kk] : 0.f;
        }
#pragma unroll
        for (int i = 0; i < 4; i++) {
            int idx = t + i * 256;
            int kk = idx >> 6, nn = idx & 63;
            sB[kk * 64 + nn] = Wkb[(size_t)(ks + kk) * 4096 + n0 + nn];
        }
        __syncthreads();
#pragma unroll
        for (int kk = 0; kk < 16; kk++) {
            float a[4], bv[4];
#pragma unroll
            for (int i = 0; i < 4; i++) a[i] = sA[kk * 65 + ty + 16 * i];
#pragma unroll
            for (int j = 0; j < 4; j++) bv[j] = sB[kk * 64 + tx + 16 * j];
#pragma unroll
            for (int i = 0; i < 4; i++)
#pragma unroll
                for (int j = 0; j < 4; j++) acc[i][j] += a[i] * bv[j];
        }
        __syncthreads();
    }
#pragma unroll
    for (int i = 0; i < 4; i++) {
        int m = m0 + ty + 16 * i;
        if (m >= 510) continue;
        int bb = (m >= NBLK) ? 1 : 0;
        int nb = m - bb * NBLK;
#pragma unroll
        for (int j = 0; j < 4; j++) {
            int ng = n0 + tx + 16 * j;
            int h = ng >> 8, d = ng & 255;
            if (d < 128)
                g_Kf[((size_t)((bb * H_ + h) * NBLK + nb)) * QKD_ + d] = acc[i][j];
            else
                g_Vf[((size_t)((bb * H_ + h) * NBLK + nb)) * VD_ + (d - 128)] = acc[i][j];
        }
    }
}

// ---------------- broadcast rope into Kf[...,128:192] ----------------
__global__ void rope_fill_kernel() {
    int i = blockIdx.x * blockDim.x + threadIdx.x;
    const int tot = B_ * H_ * NBLK * ROPE_;
    if (i >= tot) return;
    int e = i & 63;
    int nb = (i >> 6) % NBLK;
    int h = (i / (64 * NBLK)) % H_;
    int b = i / (64 * NBLK * H_);
    g_Kf[((size_t)((b * H_ + h) * NBLK + nb)) * QKD_ + 128 + e] = g_cmp_pe[((size_t)(b * NBLK + nb)) * 64 + e];
}

// ---------------- attention: 32 queries per block, full score row in smem ----
// smem: sQ 32x192 | sS 32x256 | sKV 128x193 (K) reused as 128x128 (V)
#define ATTN_SMEM_FLOATS (32 * 192 + 32 * 256 + 128 * 193)

__global__ void attn_kernel(const float* __restrict__ q, float* __restrict__ out)
{
    extern __shared__ float sm[];
    float* sQ  = sm;
    float* sS  = sm + 32 * 192;
    float* sKV = sm + 32 * 192 + 32 * 256;

    const int qt = blockIdx.x, h = blockIdx.y, b = blockIdx.z;
    const int s0 = qt * 32;
    const int t = threadIdx.x;
    const int ty = t >> 5, tx = t & 31;

    // load Q tile (rows contiguous 192 floats, stride H*192)
    const float* qb = q + ((size_t)(b * S_ + s0) * H_ + h) * QKD_;
    for (int i = t; i < 32 * 48; i += 256) {
        int r = i / 48, c = i % 48;
        ((float4*)sQ)[r * 48 + c] = ((const float4*)(qb + (size_t)r * H_ * QKD_))[c];
    }

    const float* Kb = g_Kf + (size_t)(b * H_ + h) * NBLK * QKD_;
    const float* Vb = g_Vf + (size_t)(b * H_ + h) * NBLK * VD_;

    // ---- scores ----
    for (int nt = 0; nt < 2; nt++) {
        int n0 = nt * 128;
        __syncthreads();
        for (int i = t; i < 128 * 192; i += 256) {
            int r = i / 192, c = i % 192;
            int n = n0 + r;
            sKV[r * 193 + c] = (n < NBLK) ? Kb[(size_t)n * QKD_ + c] : 0.f;
        }
        __syncthreads();
        float acc[4][4];
#pragma unroll
        for (int i = 0; i < 4; i++)
#pragma unroll
            for (int j = 0; j < 4; j++) acc[i][j] = 0.f;
        const float* qr = sQ + (ty * 4) * 192;
        const float* kr = sKV + tx * 193;
#pragma unroll 2
        for (int d = 0; d < 192; d++) {
            float a0 = qr[d], a1 = qr[192 + d], a2 = qr[384 + d], a3 = qr[576 + d];
            float b0 = kr[d], b1 = kr[32 * 193 + d], b2 = kr[64 * 193 + d], b3 = kr[96 * 193 + d];
            acc[0][0] += a0 * b0; acc[0][1] += a0 * b1; acc[0][2] += a0 * b2; acc[0][3] += a0 * b3;
            acc[1][0] += a1 * b0; acc[1][1] += a1 * b1; acc[1][2] += a1 * b2; acc[1][3] += a1 * b3;
            acc[2][0] += a2 * b0; acc[2][1] += a2 * b1; acc[2][2] += a2 * b2; acc[2][3] += a2 * b3;
            acc[3][0] += a3 * b0; acc[3][1] += a3 * b1; acc[3][2] += a3 * b2; acc[3][3] += a3 * b3;
        }
#pragma unroll
        for (int i = 0; i < 4; i++)
#pragma unroll
            for (int j = 0; j < 4; j++)
                sS[(ty * 4 + i) * 256 + n0 + tx + 32 * j] = acc[i][j];
    }
    __syncthreads();

    // ---- softmax + p_agg (warp ty handles rows ty*4..ty*4+3) ----
    for (int rr = 0; rr < 4; rr++) {
        int r = ty * 4 + rr;
        int s = s0 + r;
        int nmax = (s >= 31) ? ((s - 31) >> 4) : -1;   // max valid compression block
        float m = -3.4e38f;
        for (int n = tx; n < 256; n += 32) {
            float v = (n <= nmax) ? sS[r * 256 + n] * SCALE_ : -3.4e38f;
            m = fmaxf(m, v);
        }
#pragma unroll
        for (int o = 16; o; o >>= 1) m = fmaxf(m, __shfl_xor_sync(0xffffffffu, m, o));
        float L = 0.f;
        for (int n = tx; n < 256; n += 32) {
            float e = 0.f;
            if (n <= nmax) e = expf(sS[r * 256 + n] * SCALE_ - m);
            sS[r * 256 + n] = e;
            L += e;
        }
#pragma unroll
        for (int o = 16; o; o >>= 1) L += __shfl_xor_sync(0xffffffffu, L, o);
        if (nmax >= 0) {
            float inv = 1.f / L;
            for (int n = tx; n <= nmax; n += 32) {
                float p = sS[r * 256 + n] * inv;
                sS[r * 256 + n] = p;
                atomicMax((int*)&g_pagg[(size_t)(b * S_ + s) * 256 + n], __float_as_int(p));
            }
        }
    }
    __syncthreads();

    // ---- O = P @ V ----
    float oa[4][4];
#pragma unroll
    for (int i = 0; i < 4; i++)
#pragma unroll
        for (int j = 0; j < 4; j++) oa[i][j] = 0.f;

    for (int nt = 0; nt < 2; nt++) {
        int n0 = nt * 128;
        __syncthreads();
        for (int i = t; i < 128 * 128; i += 256) {
            int r = i >> 7, c = i & 127;
            int n = n0 + r;
            sKV[i] = (n < NBLK) ? Vb[(size_t)n * VD_ + c] : 0.f;
        }
        __syncthreads();
        const float* pr = sS + (ty * 4) * 256 + n0;
#pragma unroll 2
        for (int nn = 0; nn < 128; nn++) {
            float p0 = pr[nn], p1 = pr[256 + nn], p2 = pr[512 + nn], p3 = pr[768 + nn];
            const float* vr = sKV + nn * 128 + tx;
            float v0 = vr[0], v1 = vr[32], v2 = vr[64], v3 = vr[96];
            oa[0][0] += p0 * v0; oa[0][1] += p0 * v1; oa[0][2] += p0 * v2; oa[0][3] += p0 * v3;
            oa[1][0] += p1 * v0; oa[1][1] += p1 * v1; oa[1][2] += p1 * v2; oa[1][3] += p1 * v3;
            oa[2][0] += p2 * v0; oa[2][1] += p2 * v1; oa[2][2] += p2 * v2; oa[2][3] += p2 * v3;
            oa[3][0] += p3 * v0; oa[3][1] += p3 * v1; oa[3][2] += p3 * v2; oa[3][3] += p3 * v3;
        }
    }
#pragma unroll
    for (int i = 0; i < 4; i++) {
        int s = s0 + ty * 4 + i;
        float* orow = out + (size_t)(b * S_ + s) * (H_ * VD_) + h * VD_;
#pragma unroll
        for (int j = 0; j < 4; j++) orow[tx + 32 * j] = oa[i][j];
    }
}

// ---------------- top-k selection ----------------
__global__ void topk_kernel(float* __restrict__ out)
{
    int idx = blockIdx.x * blockDim.x + threadIdx.x;   // b*S + s
    if (idx >= B_ * S_) return;
    int s = idx & (S_ - 1);
    int jt = s >> 6;
    const float* pa = g_pagg + (size_t)idx * 256;

    float sc[64];
#pragma unroll 1
    for (int j = 0; j < 64; j++) {
        if (j > jt)               { sc[j] = -1e9f; continue; }   // not causal
        if (j == 0 || j >= jt - 1){ sc[j] =  1e9f; continue; }   // forced
        int nlo = 4 * j - 1;                                      // j>=1 so >=3
        int nhi = min(NBLK - 1, 4 * j + 3);
        float sum = 0.f;
        for (int n = nlo; n <= nhi; n++) sum += pa[n];
        sc[j] = sum;
    }
    float* o = out + (size_t)B_ * S_ * (H_ * VD_) + (size_t)idx * TOPK_;
#pragma unroll 1
    for (int k = 0; k < TOPK_; k++) {
        float best = -3.4e38f; int bi = 0;
        for (int j = 0; j < 64; j++)
            if (sc[j] > best) { best = sc[j]; bi = j; }   // strict > keeps lowest index on tie (jax semantics)
        o[k] = (best <= -5e8f) ? -1.f : (float)bi;
        sc[bi] = -3.4e38f;
    }
}

// ---------------- launch ----------------
extern "C" void kernel_launch(void* const* d_in, const int* in_sizes, int n_in,
                              void* d_out, int out_size)
{
    const float* q       = (const float*)d_in[0];
    const float* kv_lora = (const float*)d_in[1];
    const float* k_pe    = (const float*)d_in[2];
    const float* Wck     = (const float*)d_in[3];
    const float* Wcp     = (const float*)d_in[4];
    const float* Wkb     = (const float*)d_in[5];
    float* out = (float*)d_out;

    cudaFuncSetAttribute(attn_kernel, cudaFuncAttributeMaxDynamicSharedMemorySize,
                         ATTN_SMEM_FLOATS * (int)sizeof(float));

    // 0) zero p_agg
    {
        size_t n = (size_t)B_ * S_ * 256;
        zero_pagg_kernel<<<(unsigned)((n + 255) / 256), 256>>>();
    }
    // 1) cmp_kv split-K: M=512(510), N=512, K=16384 in 8 chunks of 2048
    gather_gemm_kernel<<<dim3(8, 8, KSPLIT), 256>>>(kv_lora, Wck, 9, 512, 2048, 0);
    // 2) cmp_pe split-K: M=512(510), N=64, K=2048 in 8 chunks of 256
    gather_gemm_kernel<<<dim3(8, 1, KSPLIT), 256>>>(k_pe, Wcp, 6, 64, 256, 1);
    // 3) reduce partials
    {
        int tot = 510 * 512 + 510 * 64;
        reduce_kernel<<<(tot + 255) / 256, 256>>>();
    }
    // 4) kvb GEMM + scatter to Kf/Vf
    kvb_gemm_kernel<<<dim3(8, 64), 256>>>(Wkb);
    // 5) rope broadcast into Kf
    {
        int tot = B_ * H_ * NBLK * ROPE_;
        rope_fill_kernel<<<(tot + 255) / 256, 256>>>();
    }
    // 6) attention (+ probs max into p_agg)
    attn_kernel<<<dim3(S_ / 32, H_, B_), 256, ATTN_SMEM_FLOATS * (int)sizeof(float)>>>(q, out);
    // 7) top-k indices
    topk_kernel<<<(B_ * S_ + 255) / 256, 256>>>(out);
}

// round 7
// speedup vs baseline: 1.7141x; 1.7141x over previous
#include <cuda_runtime.h>
#include <cstdint>

// ---------------- problem constants ----------------
#define B_    2
#define S_    4096
#define H_    16
#define NBLK  255
#define R_    512
#define ROPE_ 64
#define QKD_  192
#define VD_   128
#define KER_  32
#define STR_  16
#define TOPK_ 16
#define SCALE_ 0.07216878364870323f

#define KSPLIT 8

// ---------------- scratch (device globals; no cudaMalloc allowed) ----------
__device__ float g_scr_kv[KSPLIT * 512 * 512];   // split-K partials for cmp_kv
__device__ float g_scr_pe[KSPLIT * 512 * 64];    // split-K partials for cmp_pe
__device__ float g_cmp_kv[510 * 512];
__device__ float g_cmp_pe[510 * 64];
__device__ float g_Kf[(size_t)B_ * H_ * NBLK * QKD_];  // per-head K (nope||rope)
__device__ float g_Vf[(size_t)B_ * H_ * NBLK * VD_];   // per-head V
__device__ float g_pagg[(size_t)B_ * S_ * 256];        // max-over-heads probs (padded nblk->256)

// ---------------- helpers ----------------
__device__ __forceinline__ float tf32r(float x) {
    unsigned r; asm("cvt.rna.tf32.f32 %0, %1;" : "=r"(r) : "f"(x));
    return __uint_as_float(r);
}
__device__ __forceinline__ void mma_tf32(float c[4],
    unsigned a0, unsigned a1, unsigned a2, unsigned a3,
    unsigned b0, unsigned b1)
{
    asm volatile(
        "mma.sync.aligned.m16n8k8.row.col.f32.tf32.tf32.f32 "
        "{%0,%1,%2,%3},{%4,%5,%6,%7},{%8,%9},{%0,%1,%2,%3};"
        : "+f"(c[0]), "+f"(c[1]), "+f"(c[2]), "+f"(c[3])
        : "r"(a0), "r"(a1), "r"(a2), "r"(a3), "r"(b0), "r"(b1));
}

// ---------------- zero p_agg ----------------
__global__ void zero_pagg_kernel() {
    size_t i = (size_t)blockIdx.x * blockDim.x + threadIdx.x;
    size_t n = (size_t)B_ * S_ * 256;
    if (i < n) g_pagg[i] = 0.f;
}

// ---------------- gathered split-K GEMM (fp32, unchanged) ----------------
__global__ void gather_gemm_kernel(const float* __restrict__ src,
                                   const float* __restrict__ W,
                                   int logF, int N, int KC, int mode)
{
    __shared__ float sA[16 * 65];
    __shared__ float sB[16 * 64];
    float* scratch = mode ? g_scr_pe : g_scr_kv;
    const int F = 1 << logF;
    const int m0 = blockIdx.x * 64, n0 = blockIdx.y * 64;
    const int k0 = blockIdx.z * KC;
    const int t = threadIdx.x;
    const int ty = t >> 4, tx = t & 15;

    float acc[4][4];
#pragma unroll
    for (int i = 0; i < 4; i++)
#pragma unroll
        for (int j = 0; j < 4; j++) acc[i][j] = 0.f;

    for (int ks = 0; ks < KC; ks += 16) {
#pragma unroll
        for (int i = 0; i < 4; i++) {
            int idx = t + i * 256;
            int mm = idx >> 4, kk = idx & 15;
            int m = m0 + mm;
            float v = 0.f;
            if (m < 510) {
                int bb = (m >= NBLK) ? 1 : 0;
                int nb = m - bb * NBLK;
                int k = k0 + ks + kk;
                int p = k >> logF, c = k & (F - 1);
                v = src[(((size_t)bb * S_ + nb * STR_ + p) << logF) + c];
            }
            sA[kk * 65 + mm] = v;
        }
#pragma unroll
        for (int i = 0; i < 4; i++) {
            int idx = t + i * 256;
            int kk = idx >> 6, nn = idx & 63;
            sB[kk * 64 + nn] = W[(size_t)(k0 + ks + kk) * N + n0 + nn];
        }
        __syncthreads();
#pragma unroll
        for (int kk = 0; kk < 16; kk++) {
            float a[4], bv[4];
#pragma unroll
            for (int i = 0; i < 4; i++) a[i] = sA[kk * 65 + ty + 16 * i];
#pragma unroll
            for (int j = 0; j < 4; j++) bv[j] = sB[kk * 64 + tx + 16 * j];
#pragma unroll
            for (int i = 0; i < 4; i++)
#pragma unroll
                for (int j = 0; j < 4; j++) acc[i][j] += a[i] * bv[j];
        }
        __syncthreads();
    }
#pragma unroll
    for (int i = 0; i < 4; i++)
#pragma unroll
        for (int j = 0; j < 4; j++)
            scratch[((size_t)blockIdx.z * 512 + m0 + ty + 16 * i) * N + n0 + tx + 16 * j] = acc[i][j];
}

// ---------------- split-K reduction ----------------
__global__ void reduce_kernel() {
    int i = blockIdx.x * blockDim.x + threadIdx.x;
    if (i < 510 * 512) {
        int m = i / 512, n = i % 512;
        float s = 0.f;
#pragma unroll
        for (int kc = 0; kc < KSPLIT; kc++) s += g_scr_kv[((size_t)kc * 512 + m) * 512 + n];
        g_cmp_kv[i] = s;
    } else if (i < 510 * 512 + 510 * 64) {
        int j = i - 510 * 512;
        int m = j / 64, e = j % 64;
        float s = 0.f;
#pragma unroll
        for (int kc = 0; kc < KSPLIT; kc++) s += g_scr_pe[((size_t)kc * 512 + m) * 64 + e];
        g_cmp_pe[j] = s;
    }
}

// ---------------- kvb GEMM with scatter into Kf/Vf (fp32, unchanged) ------
__global__ void kvb_gemm_kernel(const float* __restrict__ Wkb)
{
    __shared__ float sA[16 * 65];
    __shared__ float sB[16 * 64];
    const int m0 = blockIdx.x * 64, n0 = blockIdx.y * 64;
    const int t = threadIdx.x;
    const int ty = t >> 4, tx = t & 15;

    float acc[4][4];
#pragma unroll
    for (int i = 0; i < 4; i++)
#pragma unroll
        for (int j = 0; j < 4; j++) acc[i][j] = 0.f;

    for (int ks = 0; ks < 512; ks += 16) {
#pragma unroll
        for (int i = 0; i < 4; i++) {
            int idx = t + i * 256;
            int mm = idx >> 4, kk = idx & 15;
            int m = m0 + mm;
            sA[kk * 65 + mm] = (m < 510) ? g_cmp_kv[(size_t)m * 512 + ks + kk] : 0.f;
        }
#pragma unroll
        for (int i = 0; i < 4; i++) {
            int idx = t + i * 256;
            int kk = idx >> 6, nn = idx & 63;
            sB[kk * 64 + nn] = Wkb[(size_t)(ks + kk) * 4096 + n0 + nn];
        }
        __syncthreads();
#pragma unroll
        for (int kk = 0; kk < 16; kk++) {
            float a[4], bv[4];
#pragma unroll
            for (int i = 0; i < 4; i++) a[i] = sA[kk * 65 + ty + 16 * i];
#pragma unroll
            for (int j = 0; j < 4; j++) bv[j] = sB[kk * 64 + tx + 16 * j];
#pragma unroll
            for (int i = 0; i < 4; i++)
#pragma unroll
                for (int j = 0; j < 4; j++) acc[i][j] += a[i] * bv[j];
        }
        __syncthreads();
    }
#pragma unroll
    for (int i = 0; i < 4; i++) {
        int m = m0 + ty + 16 * i;
        if (m >= 510) continue;
        int bb = (m >= NBLK) ? 1 : 0;
        int nb = m - bb * NBLK;
#pragma unroll
        for (int j = 0; j < 4; j++) {
            int ng = n0 + tx + 16 * j;
            int h = ng >> 8, d = ng & 255;
            if (d < 128)
                g_Kf[((size_t)((bb * H_ + h) * NBLK + nb)) * QKD_ + d] = acc[i][j];
            else
                g_Vf[((size_t)((bb * H_ + h) * NBLK + nb)) * VD_ + (d - 128)] = acc[i][j];
        }
    }
}

// ---------------- broadcast rope into Kf[...,128:192] ----------------
__global__ void rope_fill_kernel() {
    int i = blockIdx.x * blockDim.x + threadIdx.x;
    const int tot = B_ * H_ * NBLK * ROPE_;
    if (i >= tot) return;
    int e = i & 63;
    int nb = (i >> 6) % NBLK;
    int h = (i / (64 * NBLK)) % H_;
    int b = i / (64 * NBLK * H_);
    g_Kf[((size_t)((b * H_ + h) * NBLK + nb)) * QKD_ + 128 + e] = g_cmp_pe[((size_t)(b * NBLK + nb)) * 64 + e];
}

// ---------------- attention: 3x-tf32-split scores + tf32 PV ----------------
// smem: sQh 32xQP | sQl 32xQP | sS 32xSP | sKh 64xKP | sKl 64xKP
// V phase reuses sKh region as 128xVP (17408 <= 25088 floats)
#define QP 196
#define SP 260
#define KP 196
#define VP 136
#define ATTN_SMEM_FLOATS (32 * QP * 2 + 32 * SP + 64 * KP * 2)

__global__ void attn_kernel(const float* __restrict__ q, float* __restrict__ out)
{
    extern __shared__ float sm[];
    float* sQh = sm;
    float* sQl = sQh + 32 * QP;
    float* sS  = sQl + 32 * QP;
    float* sKh = sS + 32 * SP;
    float* sKl = sKh + 64 * KP;
    float* sKV = sKh;   // V phase reuse

    const int qt = blockIdx.x, h = blockIdx.y, b = blockIdx.z;
    const int s0 = qt * 32;
    const int t = threadIdx.x;
    const int w = t >> 5, lane = t & 31;
    const int g = lane >> 2, tig = lane & 3;
    const int mrow = 16 * (w & 1);     // warp's m offset (0 or 16)

    // ---- load Q tile, hi/lo tf32 split ----
    const float* qb = q + ((size_t)(b * S_ + s0) * H_ + h) * QKD_;
    for (int i = t; i < 32 * 48; i += 256) {
        int r = i / 48, c = i % 48;
        float4 v = ((const float4*)(qb + (size_t)r * H_ * QKD_))[c];
        float hx = tf32r(v.x), hy = tf32r(v.y), hz = tf32r(v.z), hw = tf32r(v.w);
        float* dh = sQh + r * QP + c * 4;
        float* dl = sQl + r * QP + c * 4;
        dh[0] = hx; dh[1] = hy; dh[2] = hz; dh[3] = hw;
        dl[0] = tf32r(v.x - hx); dl[1] = tf32r(v.y - hy);
        dl[2] = tf32r(v.z - hz); dl[3] = tf32r(v.w - hw);
    }

    const float* Kb = g_Kf + (size_t)(b * H_ + h) * NBLK * QKD_;
    const float* Vb = g_Vf + (size_t)(b * H_ + h) * NBLK * VD_;

    // ---- scores: S[32 x 256] = Q[32x192] . K^T, K in four 64-row tiles ----
    const int nloc = (w >> 1) * 16;     // warp column base within 64-wide tile
    for (int nt = 0; nt < 4; nt++) {
        int n0t = nt * 64;
        __syncthreads();
        for (int i = t; i < 64 * 48; i += 256) {
            int r = i / 48, c = i % 48;
            int n = n0t + r;
            float4 v = (n < NBLK) ? ((const float4*)(Kb + (size_t)n * QKD_))[c]
                                  : make_float4(0.f, 0.f, 0.f, 0.f);
            float hx = tf32r(v.x), hy = tf32r(v.y), hz = tf32r(v.z), hw = tf32r(v.w);
            float* dh = sKh + r * KP + c * 4;
            float* dl = sKl + r * KP + c * 4;
            dh[0] = hx; dh[1] = hy; dh[2] = hz; dh[3] = hw;
            dl[0] = tf32r(v.x - hx); dl[1] = tf32r(v.y - hy);
            dl[2] = tf32r(v.z - hz); dl[3] = tf32r(v.w - hw);
        }
        __syncthreads();

        float acc[2][4];
#pragma unroll
        for (int j = 0; j < 2; j++)
#pragma unroll
            for (int e = 0; e < 4; e++) acc[j][e] = 0.f;

#pragma unroll 4
        for (int k0 = 0; k0 < 192; k0 += 8) {
            unsigned ah0 = __float_as_uint(sQh[(mrow + g) * QP + k0 + tig]);
            unsigned ah1 = __float_as_uint(sQh[(mrow + g + 8) * QP + k0 + tig]);
            unsigned ah2 = __float_as_uint(sQh[(mrow + g) * QP + k0 + tig + 4]);
            unsigned ah3 = __float_as_uint(sQh[(mrow + g + 8) * QP + k0 + tig + 4]);
            unsigned al0 = __float_as_uint(sQl[(mrow + g) * QP + k0 + tig]);
            unsigned al1 = __float_as_uint(sQl[(mrow + g + 8) * QP + k0 + tig]);
            unsigned al2 = __float_as_uint(sQl[(mrow + g) * QP + k0 + tig + 4]);
            unsigned al3 = __float_as_uint(sQl[(mrow + g + 8) * QP + k0 + tig + 4]);
#pragma unroll
            for (int j = 0; j < 2; j++) {
                int row = nloc + j * 8 + g;
                unsigned bh0 = __float_as_uint(sKh[row * KP + k0 + tig]);
                unsigned bh1 = __float_as_uint(sKh[row * KP + k0 + tig + 4]);
                unsigned bl0 = __float_as_uint(sKl[row * KP + k0 + tig]);
                unsigned bl1 = __float_as_uint(sKl[row * KP + k0 + tig + 4]);
                mma_tf32(acc[j], ah0, ah1, ah2, ah3, bh0, bh1);
                mma_tf32(acc[j], al0, al1, al2, al3, bh0, bh1);
                mma_tf32(acc[j], ah0, ah1, ah2, ah3, bl0, bl1);
            }
        }
#pragma unroll
        for (int j = 0; j < 2; j++) {
            int col = n0t + nloc + j * 8 + 2 * tig;
            *(float2*)(sS + (mrow + g) * SP + col)     = make_float2(acc[j][0], acc[j][1]);
            *(float2*)(sS + (mrow + g + 8) * SP + col) = make_float2(acc[j][2], acc[j][3]);
        }
    }
    __syncthreads();

    // ---- softmax + p_agg in full fp32 (warp w handles rows w*4..w*4+3) ----
    const int tx = lane;
    for (int rr = 0; rr < 4; rr++) {
        int r = w * 4 + rr;
        int s = s0 + r;
        int nmax = (s >= 31) ? ((s - 31) >> 4) : -1;   // max valid compression block
        float m = -3.4e38f;
        for (int n = tx; n < 256; n += 32) {
            float v = (n <= nmax) ? sS[r * SP + n] * SCALE_ : -3.4e38f;
            m = fmaxf(m, v);
        }
#pragma unroll
        for (int o = 16; o; o >>= 1) m = fmaxf(m, __shfl_xor_sync(0xffffffffu, m, o));
        float L = 0.f;
        for (int n = tx; n < 256; n += 32) {
            float e = 0.f;
            if (n <= nmax) e = expf(sS[r * SP + n] * SCALE_ - m);
            sS[r * SP + n] = e;
            L += e;
        }
#pragma unroll
        for (int o = 16; o; o >>= 1) L += __shfl_xor_sync(0xffffffffu, L, o);
        if (nmax >= 0) {
            float inv = 1.f / L;
            for (int n = tx; n <= nmax; n += 32) {
                float p = sS[r * SP + n] * inv;       // full fp32
                sS[r * SP + n] = p;
                atomicMax((int*)&g_pagg[(size_t)(b * S_ + s) * 256 + n], __float_as_int(p));
            }
        }
    }

    // ---- O[32x128] = P[32x256] . V[256x128] (single-pass tf32) ----
    const int nquad = w >> 1;
    float oa[4][4];
#pragma unroll
    for (int j = 0; j < 4; j++)
#pragma unroll
        for (int e = 0; e < 4; e++) oa[j][e] = 0.f;

    for (int nt = 0; nt < 2; nt++) {
        int n0t = nt * 128;
        __syncthreads();
        for (int i = t; i < 128 * 32; i += 256) {
            int r = i / 32, c = i % 32;
            int n = n0t + r;
            float4 v = (n < NBLK) ? ((const float4*)(Vb + (size_t)n * VD_))[c]
                                  : make_float4(0.f, 0.f, 0.f, 0.f);
            float* dst = sKV + r * VP + c * 4;
            dst[0] = tf32r(v.x); dst[1] = tf32r(v.y); dst[2] = tf32r(v.z); dst[3] = tf32r(v.w);
        }
        __syncthreads();

        const int vbase = nquad * 32;
#pragma unroll 4
        for (int ks = 0; ks < 128; ks += 8) {
            int k0 = n0t + ks;
            unsigned a0 = __float_as_uint(tf32r(sS[(mrow + g) * SP + k0 + tig]));
            unsigned a1 = __float_as_uint(tf32r(sS[(mrow + g + 8) * SP + k0 + tig]));
            unsigned a2 = __float_as_uint(tf32r(sS[(mrow + g) * SP + k0 + tig + 4]));
            unsigned a3 = __float_as_uint(tf32r(sS[(mrow + g + 8) * SP + k0 + tig + 4]));
#pragma unroll
            for (int j = 0; j < 4; j++) {
                const float* vb = sKV + (ks + tig) * VP + vbase + j * 8 + g;
                unsigned b0 = __float_as_uint(vb[0]);
                unsigned b1 = __float_as_uint(vb[4 * VP]);
                mma_tf32(oa[j], a0, a1, a2, a3, b0, b1);
            }
        }
    }

    // ---- write O ----
#pragma unroll
    for (int j = 0; j < 4; j++) {
        int col = nquad * 32 + j * 8 + 2 * tig;
        {
            int s = s0 + mrow + g;
            float* orow = out + (size_t)(b * S_ + s) * (H_ * VD_) + h * VD_ + col;
            *(float2*)orow = make_float2(oa[j][0], oa[j][1]);
        }
        {
            int s = s0 + mrow + g + 8;
            float* orow = out + (size_t)(b * S_ + s) * (H_ * VD_) + h * VD_ + col;
            *(float2*)orow = make_float2(oa[j][2], oa[j][3]);
        }
    }
}

// ---------------- top-k selection ----------------
__global__ void topk_kernel(float* __restrict__ out)
{
    int idx = blockIdx.x * blockDim.x + threadIdx.x;   // b*S + s
    if (idx >= B_ * S_) return;
    int s = idx & (S_ - 1);
    int jt = s >> 6;
    const float* pa = g_pagg + (size_t)idx * 256;

    float sc[64];
#pragma unroll 1
    for (int j = 0; j < 64; j++) {
        if (j > jt)                { sc[j] = -1e9f; continue; }   // not causal
        if (j == 0 || j >= jt - 1) { sc[j] =  1e9f; continue; }   // forced
        int nlo = 4 * j - 1;                                      // j>=1 so >=3
        int nhi = min(NBLK - 1, 4 * j + 3);
        float sum = 0.f;
        for (int n = nlo; n <= nhi; n++) sum += pa[n];
        sc[j] = sum;
    }
    float* o = out + (size_t)B_ * S_ * (H_ * VD_) + (size_t)idx * TOPK_;
#pragma unroll 1
    for (int k = 0; k < TOPK_; k++) {
        float best = -3.4e38f; int bi = 0;
        for (int j = 0; j < 64; j++)
            if (sc[j] > best) { best = sc[j]; bi = j; }   // strict > keeps lowest index on tie
        o[k] = (best <= -5e8f) ? -1.f : (float)bi;
        sc[bi] = -3.4e38f;
    }
}

// ---------------- launch ----------------
extern "C" void kernel_launch(void* const* d_in, const int* in_sizes, int n_in,
                              void* d_out, int out_size)
{
    const float* q       = (const float*)d_in[0];
    const float* kv_lora = (const float*)d_in[1];
    const float* k_pe    = (const float*)d_in[2];
    const float* Wck     = (const float*)d_in[3];
    const float* Wcp     = (const float*)d_in[4];
    const float* Wkb     = (const float*)d_in[5];
    float* out = (float*)d_out;

    cudaFuncSetAttribute(attn_kernel, cudaFuncAttributeMaxDynamicSharedMemorySize,
                         ATTN_SMEM_FLOATS * (int)sizeof(float));

    // 0) zero p_agg
    {
        size_t n = (size_t)B_ * S_ * 256;
        zero_pagg_kernel<<<(unsigned)((n + 255) / 256), 256>>>();
    }
    // 1) cmp_kv split-K: M=512(510), N=512, K=16384 in 8 chunks of 2048
    gather_gemm_kernel<<<dim3(8, 8, KSPLIT), 256>>>(kv_lora, Wck, 9, 512, 2048, 0);
    // 2) cmp_pe split-K: M=512(510), N=64, K=2048 in 8 chunks of 256
    gather_gemm_kernel<<<dim3(8, 1, KSPLIT), 256>>>(k_pe, Wcp, 6, 64, 256, 1);
    // 3) reduce partials
    {
        int tot = 510 * 512 + 510 * 64;
        reduce_kernel<<<(tot + 255) / 256, 256>>>();
    }
    // 4) kvb GEMM + scatter to Kf/Vf
    kvb_gemm_kernel<<<dim3(8, 64), 256>>>(Wkb);
    // 5) rope broadcast into Kf
    {
        int tot = B_ * H_ * NBLK * ROPE_;
        rope_fill_kernel<<<(tot + 255) / 256, 256>>>();
    }
    // 6) attention (+ probs max into p_agg)
    attn_kernel<<<dim3(S_ / 32, H_, B_), 256, ATTN_SMEM_FLOATS * (int)sizeof(float)>>>(q, out);
    // 7) top-k indices
    topk_kernel<<<(B_ * S_ + 255) / 256, 256>>>(out);
}

// round 8
// speedup vs baseline: 2.0235x; 1.1805x over previous
#include <cuda_runtime.h>
#include <cstdint>

// ---------------- problem constants ----------------
#define B_    2
#define S_    4096
#define H_    16
#define NBLK  255
#define R_    512
#define ROPE_ 64
#define QKD_  192
#define VD_   128
#define KER_  32
#define STR_  16
#define TOPK_ 16
#define SCALE_ 0.07216878364870323f

#define KSPLIT 8

// ---------------- scratch (device globals; no cudaMalloc allowed) ----------
__device__ float g_scr_kv[KSPLIT * 512 * 512];   // split-K partials for cmp_kv
__device__ float g_scr_pe[KSPLIT * 512 * 64];    // split-K partials for cmp_pe
__device__ float g_cmp_kv[510 * 512];
__device__ float g_cmp_pe[510 * 64];
__device__ float g_Kf[(size_t)B_ * H_ * NBLK * QKD_];  // per-head K (nope||rope)
__device__ float g_Vf[(size_t)B_ * H_ * NBLK * VD_];   // per-head V
__device__ float g_pagg[(size_t)B_ * S_ * 256];        // max-over-heads probs (padded nblk->256)

// ---------------- helpers ----------------
__device__ __forceinline__ float tf32r(float x) {
    unsigned r; asm("cvt.rna.tf32.f32 %0, %1;" : "=r"(r) : "f"(x));
    return __uint_as_float(r);
}
__device__ __forceinline__ void mma_tf32(float c[4],
    unsigned a0, unsigned a1, unsigned a2, unsigned a3,
    unsigned b0, unsigned b1)
{
    asm volatile(
        "mma.sync.aligned.m16n8k8.row.col.f32.tf32.tf32.f32 "
        "{%0,%1,%2,%3},{%4,%5,%6,%7},{%8,%9},{%0,%1,%2,%3};"
        : "+f"(c[0]), "+f"(c[1]), "+f"(c[2]), "+f"(c[3])
        : "r"(a0), "r"(a1), "r"(a2), "r"(a3), "r"(b0), "r"(b1));
}

// ---------------- zero p_agg ----------------
__global__ void zero_pagg_kernel() {
    size_t i = (size_t)blockIdx.x * blockDim.x + threadIdx.x;
    size_t n = (size_t)B_ * S_ * 256;
    if (i < n) g_pagg[i] = 0.f;
}

// ---------------- gathered split-K GEMM (fp32) ----------------
__global__ void gather_gemm_kernel(const float* __restrict__ src,
                                   const float* __restrict__ W,
                                   int logF, int N, int KC, int mode)
{
    __shared__ float sA[16 * 65];
    __shared__ float sB[16 * 64];
    float* scratch = mode ? g_scr_pe : g_scr_kv;
    const int F = 1 << logF;
    const int m0 = blockIdx.x * 64, n0 = blockIdx.y * 64;
    const int k0 = blockIdx.z * KC;
    const int t = threadIdx.x;
    const int ty = t >> 4, tx = t & 15;

    float acc[4][4];
#pragma unroll
    for (int i = 0; i < 4; i++)
#pragma unroll
        for (int j = 0; j < 4; j++) acc[i][j] = 0.f;

    for (int ks = 0; ks < KC; ks += 16) {
#pragma unroll
        for (int i = 0; i < 4; i++) {
            int idx = t + i * 256;
            int mm = idx >> 4, kk = idx & 15;
            int m = m0 + mm;
            float v = 0.f;
            if (m < 510) {
                int bb = (m >= NBLK) ? 1 : 0;
                int nb = m - bb * NBLK;
                int k = k0 + ks + kk;
                int p = k >> logF, c = k & (F - 1);
                v = src[(((size_t)bb * S_ + nb * STR_ + p) << logF) + c];
            }
            sA[kk * 65 + mm] = v;
        }
#pragma unroll
        for (int i = 0; i < 4; i++) {
            int idx = t + i * 256;
            int kk = idx >> 6, nn = idx & 63;
            sB[kk * 64 + nn] = W[(size_t)(k0 + ks + kk) * N + n0 + nn];
        }
        __syncthreads();
#pragma unroll
        for (int kk = 0; kk < 16; kk++) {
            float a[4], bv[4];
#pragma unroll
            for (int i = 0; i < 4; i++) a[i] = sA[kk * 65 + ty + 16 * i];
#pragma unroll
            for (int j = 0; j < 4; j++) bv[j] = sB[kk * 64 + tx + 16 * j];
#pragma unroll
            for (int i = 0; i < 4; i++)
#pragma unroll
                for (int j = 0; j < 4; j++) acc[i][j] += a[i] * bv[j];
        }
        __syncthreads();
    }
#pragma unroll
    for (int i = 0; i < 4; i++)
#pragma unroll
        for (int j = 0; j < 4; j++)
            scratch[((size_t)blockIdx.z * 512 + m0 + ty + 16 * i) * N + n0 + tx + 16 * j] = acc[i][j];
}

// ---------------- split-K reduction ----------------
__global__ void reduce_kernel() {
    int i = blockIdx.x * blockDim.x + threadIdx.x;
    if (i < 510 * 512) {
        int m = i / 512, n = i % 512;
        float s = 0.f;
#pragma unroll
        for (int kc = 0; kc < KSPLIT; kc++) s += g_scr_kv[((size_t)kc * 512 + m) * 512 + n];
        g_cmp_kv[i] = s;
    } else if (i < 510 * 512 + 510 * 64) {
        int j = i - 510 * 512;
        int m = j / 64, e = j % 64;
        float s = 0.f;
#pragma unroll
        for (int kc = 0; kc < KSPLIT; kc++) s += g_scr_pe[((size_t)kc * 512 + m) * 64 + e];
        g_cmp_pe[j] = s;
    }
}

// ---------------- kvb GEMM with scatter into Kf/Vf (fp32) ------
__global__ void kvb_gemm_kernel(const float* __restrict__ Wkb)
{
    __shared__ float sA[16 * 65];
    __shared__ float sB[16 * 64];
    const int m0 = blockIdx.x * 64, n0 = blockIdx.y * 64;
    const int t = threadIdx.x;
    const int ty = t >> 4, tx = t & 15;

    float acc[4][4];
#pragma unroll
    for (int i = 0; i < 4; i++)
#pragma unroll
        for (int j = 0; j < 4; j++) acc[i][j] = 0.f;

    for (int ks = 0; ks < 512; ks += 16) {
#pragma unroll
        for (int i = 0; i < 4; i++) {
            int idx = t + i * 256;
            int mm = idx >> 4, kk = idx & 15;
            int m = m0 + mm;
            sA[kk * 65 + mm] = (m < 510) ? g_cmp_kv[(size_t)m * 512 + ks + kk] : 0.f;
        }
#pragma unroll
        for (int i = 0; i < 4; i++) {
            int idx = t + i * 256;
            int kk = idx >> 6, nn = idx & 63;
            sB[kk * 64 + nn] = Wkb[(size_t)(ks + kk) * 4096 + n0 + nn];
        }
        __syncthreads();
#pragma unroll
        for (int kk = 0; kk < 16; kk++) {
            float a[4], bv[4];
#pragma unroll
            for (int i = 0; i < 4; i++) a[i] = sA[kk * 65 + ty + 16 * i];
#pragma unroll
            for (int j = 0; j < 4; j++) bv[j] = sB[kk * 64 + tx + 16 * j];
#pragma unroll
            for (int i = 0; i < 4; i++)
#pragma unroll
                for (int j = 0; j < 4; j++) acc[i][j] += a[i] * bv[j];
        }
        __syncthreads();
    }
#pragma unroll
    for (int i = 0; i < 4; i++) {
        int m = m0 + ty + 16 * i;
        if (m >= 510) continue;
        int bb = (m >= NBLK) ? 1 : 0;
        int nb = m - bb * NBLK;
#pragma unroll
        for (int j = 0; j < 4; j++) {
            int ng = n0 + tx + 16 * j;
            int h = ng >> 8, d = ng & 255;
            if (d < 128)
                g_Kf[((size_t)((bb * H_ + h) * NBLK + nb)) * QKD_ + d] = acc[i][j];
            else
                g_Vf[((size_t)((bb * H_ + h) * NBLK + nb)) * VD_ + (d - 128)] = acc[i][j];
        }
    }
}

// ---------------- broadcast rope into Kf[...,128:192] ----------------
__global__ void rope_fill_kernel() {
    int i = blockIdx.x * blockDim.x + threadIdx.x;
    const int tot = B_ * H_ * NBLK * ROPE_;
    if (i >= tot) return;
    int e = i & 63;
    int nb = (i >> 6) % NBLK;
    int h = (i / (64 * NBLK)) % H_;
    int b = i / (64 * NBLK * H_);
    g_Kf[((size_t)((b * H_ + h) * NBLK + nb)) * QKD_ + 128 + e] = g_cmp_pe[((size_t)(b * NBLK + nb)) * 64 + e];
}

// ---------------- attention: 3x-tf32-split scores + tf32 PV ----------------
// Causal tile skipping: query tile at s0 needs only cols n <= s0>>4.
// smem: sQh 32xQP | sQl 32xQP | sS 32xSP | sKh 64xKP | sKl 64xKP
// V phase reuses sKh region as 128xVP
#define QP 196
#define SP 260
#define KP 196
#define VP 136
#define ATTN_SMEM_FLOATS (32 * QP * 2 + 32 * SP + 64 * KP * 2)

__global__ void attn_kernel(const float* __restrict__ q, float* __restrict__ out)
{
    extern __shared__ float sm[];
    float* sQh = sm;
    float* sQl = sQh + 32 * QP;
    float* sS  = sQl + 32 * QP;
    float* sKh = sS + 32 * SP;
    float* sKl = sKh + 64 * KP;
    float* sKV = sKh;   // V phase reuse

    const int qt = blockIdx.x, h = blockIdx.y, b = blockIdx.z;
    const int s0 = qt * 32;
    const int t = threadIdx.x;
    const int w = t >> 5, lane = t & 31;
    const int g = lane >> 2, tig = lane & 3;
    const int mrow = 16 * (w & 1);     // warp's m offset (0 or 16)

    // causal extents for this query tile
    const int nmax_tile = s0 >> 4;                       // max valid col over tile
    const int nkt = min(4, nmax_tile / 64 + 1);          // K tiles (64 cols each)
    const int nvt = min(2, nmax_tile / 128 + 1);         // V tiles (128 cols each)
    const int ncols = nvt * 128;                         // columns PV will read

    // ---- load Q tile, hi/lo tf32 split ----
    const float* qb = q + ((size_t)(b * S_ + s0) * H_ + h) * QKD_;
    for (int i = t; i < 32 * 48; i += 256) {
        int r = i / 48, c = i % 48;
        float4 v = ((const float4*)(qb + (size_t)r * H_ * QKD_))[c];
        float hx = tf32r(v.x), hy = tf32r(v.y), hz = tf32r(v.z), hw = tf32r(v.w);
        float* dh = sQh + r * QP + c * 4;
        float* dl = sQl + r * QP + c * 4;
        dh[0] = hx; dh[1] = hy; dh[2] = hz; dh[3] = hw;
        dl[0] = tf32r(v.x - hx); dl[1] = tf32r(v.y - hy);
        dl[2] = tf32r(v.z - hz); dl[3] = tf32r(v.w - hw);
    }

    const float* Kb = g_Kf + (size_t)(b * H_ + h) * NBLK * QKD_;
    const float* Vb = g_Vf + (size_t)(b * H_ + h) * NBLK * VD_;

    // ---- scores: S[32 x ncols] = Q[32x192] . K^T, K in 64-row tiles ----
    const int nloc = (w >> 1) * 16;     // warp column base within 64-wide tile
    for (int nt = 0; nt < nkt; nt++) {
        int n0t = nt * 64;
        __syncthreads();
        for (int i = t; i < 64 * 48; i += 256) {
            int r = i / 48, c = i % 48;
            int n = n0t + r;
            float4 v = (n < NBLK) ? ((const float4*)(Kb + (size_t)n * QKD_))[c]
                                  : make_float4(0.f, 0.f, 0.f, 0.f);
            float hx = tf32r(v.x), hy = tf32r(v.y), hz = tf32r(v.z), hw = tf32r(v.w);
            float* dh = sKh + r * KP + c * 4;
            float* dl = sKl + r * KP + c * 4;
            dh[0] = hx; dh[1] = hy; dh[2] = hz; dh[3] = hw;
            dl[0] = tf32r(v.x - hx); dl[1] = tf32r(v.y - hy);
            dl[2] = tf32r(v.z - hz); dl[3] = tf32r(v.w - hw);
        }
        __syncthreads();

        float acc[2][4];
#pragma unroll
        for (int j = 0; j < 2; j++)
#pragma unroll
            for (int e = 0; e < 4; e++) acc[j][e] = 0.f;

#pragma unroll 4
        for (int k0 = 0; k0 < 192; k0 += 8) {
            unsigned ah0 = __float_as_uint(sQh[(mrow + g) * QP + k0 + tig]);
            unsigned ah1 = __float_as_uint(sQh[(mrow + g + 8) * QP + k0 + tig]);
            unsigned ah2 = __float_as_uint(sQh[(mrow + g) * QP + k0 + tig + 4]);
            unsigned ah3 = __float_as_uint(sQh[(mrow + g + 8) * QP + k0 + tig + 4]);
            unsigned al0 = __float_as_uint(sQl[(mrow + g) * QP + k0 + tig]);
            unsigned al1 = __float_as_uint(sQl[(mrow + g + 8) * QP + k0 + tig]);
            unsigned al2 = __float_as_uint(sQl[(mrow + g) * QP + k0 + tig + 4]);
            unsigned al3 = __float_as_uint(sQl[(mrow + g + 8) * QP + k0 + tig + 4]);
#pragma unroll
            for (int j = 0; j < 2; j++) {
                int row = nloc + j * 8 + g;
                unsigned bh0 = __float_as_uint(sKh[row * KP + k0 + tig]);
                unsigned bh1 = __float_as_uint(sKh[row * KP + k0 + tig + 4]);
                unsigned bl0 = __float_as_uint(sKl[row * KP + k0 + tig]);
                unsigned bl1 = __float_as_uint(sKl[row * KP + k0 + tig + 4]);
                mma_tf32(acc[j], ah0, ah1, ah2, ah3, bh0, bh1);
                mma_tf32(acc[j], al0, al1, al2, al3, bh0, bh1);
                mma_tf32(acc[j], ah0, ah1, ah2, ah3, bl0, bl1);
            }
        }
#pragma unroll
        for (int j = 0; j < 2; j++) {
            int col = n0t + nloc + j * 8 + 2 * tig;
            *(float2*)(sS + (mrow + g) * SP + col)     = make_float2(acc[j][0], acc[j][1]);
            *(float2*)(sS + (mrow + g + 8) * SP + col) = make_float2(acc[j][2], acc[j][3]);
        }
    }
    __syncthreads();

    // ---- softmax + p_agg in full fp32 (warp w handles rows w*4..w*4+3) ----
    const int tx = lane;
    for (int rr = 0; rr < 4; rr++) {
        int r = w * 4 + rr;
        int s = s0 + r;
        int nmax = (s >= 31) ? ((s - 31) >> 4) : -1;   // max valid compression block
        float m = -3.4e38f;
        for (int n = tx; n <= nmax; n += 32)
            m = fmaxf(m, sS[r * SP + n] * SCALE_);
#pragma unroll
        for (int o = 16; o; o >>= 1) m = fmaxf(m, __shfl_xor_sync(0xffffffffu, m, o));
        float L = 0.f;
        for (int n = tx; n < ncols; n += 32) {
            float e = 0.f;
            if (n <= nmax) e = __expf(sS[r * SP + n] * SCALE_ - m);
            sS[r * SP + n] = e;          // zero-fills PV-visible range
            L += e;
        }
#pragma unroll
        for (int o = 16; o; o >>= 1) L += __shfl_xor_sync(0xffffffffu, L, o);
        if (nmax >= 0) {
            float inv = 1.f / L;
            for (int n = tx; n <= nmax; n += 32) {
                float p = sS[r * SP + n] * inv;       // full fp32
                sS[r * SP + n] = p;
                atomicMax((int*)&g_pagg[(size_t)(b * S_ + s) * 256 + n], __float_as_int(p));
            }
        }
    }

    // ---- O[32x128] = P[32xncols] . V[ncols x 128] (single-pass tf32) ----
    const int nquad = w >> 1;
    float oa[4][4];
#pragma unroll
    for (int j = 0; j < 4; j++)
#pragma unroll
        for (int e = 0; e < 4; e++) oa[j][e] = 0.f;

    for (int nt = 0; nt < nvt; nt++) {
        int n0t = nt * 128;
        __syncthreads();
        for (int i = t; i < 128 * 32; i += 256) {
            int r = i / 32, c = i % 32;
            int n = n0t + r;
            float4 v = (n < NBLK) ? ((const float4*)(Vb + (size_t)n * VD_))[c]
                                  : make_float4(0.f, 0.f, 0.f, 0.f);
            float* dst = sKV + r * VP + c * 4;
            dst[0] = tf32r(v.x); dst[1] = tf32r(v.y); dst[2] = tf32r(v.z); dst[3] = tf32r(v.w);
        }
        __syncthreads();

        const int vbase = nquad * 32;
#pragma unroll 4
        for (int ks = 0; ks < 128; ks += 8) {
            int k0 = n0t + ks;
            unsigned a0 = __float_as_uint(tf32r(sS[(mrow + g) * SP + k0 + tig]));
            unsigned a1 = __float_as_uint(tf32r(sS[(mrow + g + 8) * SP + k0 + tig]));
            unsigned a2 = __float_as_uint(tf32r(sS[(mrow + g) * SP + k0 + tig + 4]));
            unsigned a3 = __float_as_uint(tf32r(sS[(mrow + g + 8) * SP + k0 + tig + 4]));
#pragma unroll
            for (int j = 0; j < 4; j++) {
                const float* vb = sKV + (ks + tig) * VP + vbase + j * 8 + g;
                unsigned b0 = __float_as_uint(vb[0]);
                unsigned b1 = __float_as_uint(vb[4 * VP]);
                mma_tf32(oa[j], a0, a1, a2, a3, b0, b1);
            }
        }
    }

    // ---- write O ----
#pragma unroll
    for (int j = 0; j < 4; j++) {
        int col = nquad * 32 + j * 8 + 2 * tig;
        {
            int s = s0 + mrow + g;
            float* orow = out + (size_t)(b * S_ + s) * (H_ * VD_) + h * VD_ + col;
            *(float2*)orow = make_float2(oa[j][0], oa[j][1]);
        }
        {
            int s = s0 + mrow + g + 8;
            float* orow = out + (size_t)(b * S_ + s) * (H_ * VD_) + h * VD_ + col;
            *(float2*)orow = make_float2(oa[j][2], oa[j][3]);
        }
    }
}

// ---------------- top-k selection ----------------
__global__ void topk_kernel(float* __restrict__ out)
{
    int idx = blockIdx.x * blockDim.x + threadIdx.x;   // b*S + s
    if (idx >= B_ * S_) return;
    int s = idx & (S_ - 1);
    int jt = s >> 6;
    const float* pa = g_pagg + (size_t)idx * 256;

    float sc[64];
#pragma unroll 1
    for (int j = 0; j < 64; j++) {
        if (j > jt)                { sc[j] = -1e9f; continue; }   // not causal
        if (j == 0 || j >= jt - 1) { sc[j] =  1e9f; continue; }   // forced
        int nlo = 4 * j - 1;                                      // j>=1 so >=3
        int nhi = min(NBLK - 1, 4 * j + 3);
        float sum = 0.f;
        for (int n = nlo; n <= nhi; n++) sum += pa[n];
        sc[j] = sum;
    }
    float* o = out + (size_t)B_ * S_ * (H_ * VD_) + (size_t)idx * TOPK_;
#pragma unroll 1
    for (int k = 0; k < TOPK_; k++) {
        float best = -3.4e38f; int bi = 0;
        for (int j = 0; j < 64; j++)
            if (sc[j] > best) { best = sc[j]; bi = j; }   // strict > keeps lowest index on tie
        o[k] = (best <= -5e8f) ? -1.f : (float)bi;
        sc[bi] = -3.4e38f;
    }
}

// ---------------- launch ----------------
extern "C" void kernel_launch(void* const* d_in, const int* in_sizes, int n_in,
                              void* d_out, int out_size)
{
    const float* q       = (const float*)d_in[0];
    const float* kv_lora = (const float*)d_in[1];
    const float* k_pe    = (const float*)d_in[2];
    const float* Wck     = (const float*)d_in[3];
    const float* Wcp     = (const float*)d_in[4];
    const float* Wkb     = (const float*)d_in[5];
    float* out = (float*)d_out;

    cudaFuncSetAttribute(attn_kernel, cudaFuncAttributeMaxDynamicSharedMemorySize,
                         ATTN_SMEM_FLOATS * (int)sizeof(float));

    // 0) zero p_agg
    {
        size_t n = (size_t)B_ * S_ * 256;
        zero_pagg_kernel<<<(unsigned)((n + 255) / 256), 256>>>();
    }
    // 1) cmp_kv split-K: M=512(510), N=512, K=16384 in 8 chunks of 2048
    gather_gemm_kernel<<<dim3(8, 8, KSPLIT), 256>>>(kv_lora, Wck, 9, 512, 2048, 0);
    // 2) cmp_pe split-K: M=512(510), N=64, K=2048 in 8 chunks of 256
    gather_gemm_kernel<<<dim3(8, 1, KSPLIT), 256>>>(k_pe, Wcp, 6, 64, 256, 1);
    // 3) reduce partials
    {
        int tot = 510 * 512 + 510 * 64;
        reduce_kernel<<<(tot + 255) / 256, 256>>>();
    }
    // 4) kvb GEMM + scatter to Kf/Vf
    kvb_gemm_kernel<<<dim3(8, 64), 256>>>(Wkb);
    // 5) rope broadcast into Kf
    {
        int tot = B_ * H_ * NBLK * ROPE_;
        rope_fill_kernel<<<(tot + 255) / 256, 256>>>();
    }
    // 6) attention (+ probs max into p_agg)
    attn_kernel<<<dim3(S_ / 32, H_, B_), 256, ATTN_SMEM_FLOATS * (int)sizeof(float)>>>(q, out);
    // 7) top-k indices
    topk_kernel<<<(B_ * S_ + 255) / 256, 256>>>(out);
}

// round 9
// speedup vs baseline: 2.4632x; 1.2173x over previous
#include <cuda_runtime.h>
#include <cstdint>

// ---------------- problem constants ----------------
#define B_    2
#define S_    4096
#define H_    16
#define NBLK  255
#define R_    512
#define ROPE_ 64
#define QKD_  192
#define VD_   128
#define KER_  32
#define STR_  16
#define TOPK_ 16
#define SCALE_ 0.07216878364870323f

#define KSPLIT 8

// ---------------- scratch (device globals; no cudaMalloc allowed) ----------
__device__ float g_scr_kv[KSPLIT * 512 * 512];   // split-K partials for cmp_kv
__device__ float g_scr_pe[KSPLIT * 512 * 64];    // split-K partials for cmp_pe
__device__ float g_cmp_kv[510 * 512];
__device__ float g_cmp_pe[510 * 64];
__device__ float g_Kf[(size_t)B_ * H_ * NBLK * QKD_];  // per-head K (nope||rope)
__device__ float g_Vf[(size_t)B_ * H_ * NBLK * VD_];   // per-head V
__device__ float g_pagg[(size_t)B_ * S_ * 256];        // max-over-heads probs (padded nblk->256)

// ---------------- helpers ----------------
__device__ __forceinline__ float tf32r(float x) {
    unsigned r; asm("cvt.rna.tf32.f32 %0, %1;" : "=r"(r) : "f"(x));
    return __uint_as_float(r);
}
__device__ __forceinline__ unsigned u32f(float x) { return __float_as_uint(x); }

__device__ __forceinline__ void mma_tf32(float c[4],
    unsigned a0, unsigned a1, unsigned a2, unsigned a3,
    unsigned b0, unsigned b1)
{
    asm volatile(
        "mma.sync.aligned.m16n8k8.row.col.f32.tf32.tf32.f32 "
        "{%0,%1,%2,%3},{%4,%5,%6,%7},{%8,%9},{%0,%1,%2,%3};"
        : "+f"(c[0]), "+f"(c[1]), "+f"(c[2]), "+f"(c[3])
        : "r"(a0), "r"(a1), "r"(a2), "r"(a3), "r"(b0), "r"(b1));
}

__device__ __forceinline__ void cp16(float* dst, const float* src, bool valid) {
    unsigned d = (unsigned)__cvta_generic_to_shared(dst);
    int sz = valid ? 16 : 0;
    asm volatile("cp.async.ca.shared.global [%0], [%1], 16, %2;\n"
                 :: "r"(d), "l"(src), "r"(sz));
}
#define CP_COMMIT() asm volatile("cp.async.commit_group;\n" ::: "memory")
#define CP_WAIT1()  asm volatile("cp.async.wait_group 1;\n" ::: "memory")
#define CP_WAIT0()  asm volatile("cp.async.wait_group 0;\n" ::: "memory")

// ---------------- zero p_agg ----------------
__global__ void zero_pagg_kernel() {
    size_t i = (size_t)blockIdx.x * blockDim.x + threadIdx.x;
    size_t n = (size_t)B_ * S_ * 256;
    if (i < n) g_pagg[i] = 0.f;
}

// ---------------- gathered split-K GEMM (fp32) ----------------
__global__ void gather_gemm_kernel(const float* __restrict__ src,
                                   const float* __restrict__ W,
                                   int logF, int N, int KC, int mode)
{
    __shared__ float sA[16 * 65];
    __shared__ float sB[16 * 64];
    float* scratch = mode ? g_scr_pe : g_scr_kv;
    const int F = 1 << logF;
    const int m0 = blockIdx.x * 64, n0 = blockIdx.y * 64;
    const int k0 = blockIdx.z * KC;
    const int t = threadIdx.x;
    const int ty = t >> 4, tx = t & 15;

    float acc[4][4];
#pragma unroll
    for (int i = 0; i < 4; i++)
#pragma unroll
        for (int j = 0; j < 4; j++) acc[i][j] = 0.f;

    for (int ks = 0; ks < KC; ks += 16) {
#pragma unroll
        for (int i = 0; i < 4; i++) {
            int idx = t + i * 256;
            int mm = idx >> 4, kk = idx & 15;
            int m = m0 + mm;
            float v = 0.f;
            if (m < 510) {
                int bb = (m >= NBLK) ? 1 : 0;
                int nb = m - bb * NBLK;
                int k = k0 + ks + kk;
                int p = k >> logF, c = k & (F - 1);
                v = src[(((size_t)bb * S_ + nb * STR_ + p) << logF) + c];
            }
            sA[kk * 65 + mm] = v;
        }
#pragma unroll
        for (int i = 0; i < 4; i++) {
            int idx = t + i * 256;
            int kk = idx >> 6, nn = idx & 63;
            sB[kk * 64 + nn] = W[(size_t)(k0 + ks + kk) * N + n0 + nn];
        }
        __syncthreads();
#pragma unroll
        for (int kk = 0; kk < 16; kk++) {
            float a[4], bv[4];
#pragma unroll
            for (int i = 0; i < 4; i++) a[i] = sA[kk * 65 + ty + 16 * i];
#pragma unroll
            for (int j = 0; j < 4; j++) bv[j] = sB[kk * 64 + tx + 16 * j];
#pragma unroll
            for (int i = 0; i < 4; i++)
#pragma unroll
                for (int j = 0; j < 4; j++) acc[i][j] += a[i] * bv[j];
        }
        __syncthreads();
    }
#pragma unroll
    for (int i = 0; i < 4; i++)
#pragma unroll
        for (int j = 0; j < 4; j++)
            scratch[((size_t)blockIdx.z * 512 + m0 + ty + 16 * i) * N + n0 + tx + 16 * j] = acc[i][j];
}

// ---------------- split-K reduction ----------------
__global__ void reduce_kernel() {
    int i = blockIdx.x * blockDim.x + threadIdx.x;
    if (i < 510 * 512) {
        int m = i / 512, n = i % 512;
        float s = 0.f;
#pragma unroll
        for (int kc = 0; kc < KSPLIT; kc++) s += g_scr_kv[((size_t)kc * 512 + m) * 512 + n];
        g_cmp_kv[i] = s;
    } else if (i < 510 * 512 + 510 * 64) {
        int j = i - 510 * 512;
        int m = j / 64, e = j % 64;
        float s = 0.f;
#pragma unroll
        for (int kc = 0; kc < KSPLIT; kc++) s += g_scr_pe[((size_t)kc * 512 + m) * 64 + e];
        g_cmp_pe[j] = s;
    }
}

// ---------------- kvb GEMM with scatter into Kf/Vf (fp32) ------
__global__ void kvb_gemm_kernel(const float* __restrict__ Wkb)
{
    __shared__ float sA[16 * 65];
    __shared__ float sB[16 * 64];
    const int m0 = blockIdx.x * 64, n0 = blockIdx.y * 64;
    const int t = threadIdx.x;
    const int ty = t >> 4, tx = t & 15;

    float acc[4][4];
#pragma unroll
    for (int i = 0; i < 4; i++)
#pragma unroll
        for (int j = 0; j < 4; j++) acc[i][j] = 0.f;

    for (int ks = 0; ks < 512; ks += 16) {
#pragma unroll
        for (int i = 0; i < 4; i++) {
            int idx = t + i * 256;
            int mm = idx >> 4, kk = idx & 15;
            int m = m0 + mm;
            sA[kk * 65 + mm] = (m < 510) ? g_cmp_kv[(size_t)m * 512 + ks + kk] : 0.f;
        }
#pragma unroll
        for (int i = 0; i < 4; i++) {
            int idx = t + i * 256;
            int kk = idx >> 6, nn = idx & 63;
            sB[kk * 64 + nn] = Wkb[(size_t)(ks + kk) * 4096 + n0 + nn];
        }
        __syncthreads();
#pragma unroll
        for (int kk = 0; kk < 16; kk++) {
            float a[4], bv[4];
#pragma unroll
            for (int i = 0; i < 4; i++) a[i] = sA[kk * 65 + ty + 16 * i];
#pragma unroll
            for (int j = 0; j < 4; j++) bv[j] = sB[kk * 64 + tx + 16 * j];
#pragma unroll
            for (int i = 0; i < 4; i++)
#pragma unroll
                for (int j = 0; j < 4; j++) acc[i][j] += a[i] * bv[j];
        }
        __syncthreads();
    }
#pragma unroll
    for (int i = 0; i < 4; i++) {
        int m = m0 + ty + 16 * i;
        if (m >= 510) continue;
        int bb = (m >= NBLK) ? 1 : 0;
        int nb = m - bb * NBLK;
#pragma unroll
        for (int j = 0; j < 4; j++) {
            int ng = n0 + tx + 16 * j;
            int h = ng >> 8, d = ng & 255;
            if (d < 128)
                g_Kf[((size_t)((bb * H_ + h) * NBLK + nb)) * QKD_ + d] = acc[i][j];
            else
                g_Vf[((size_t)((bb * H_ + h) * NBLK + nb)) * VD_ + (d - 128)] = acc[i][j];
        }
    }
}

// ---------------- broadcast rope into Kf[...,128:192] ----------------
__global__ void rope_fill_kernel() {
    int i = blockIdx.x * blockDim.x + threadIdx.x;
    const int tot = B_ * H_ * NBLK * ROPE_;
    if (i >= tot) return;
    int e = i & 63;
    int nb = (i >> 6) % NBLK;
    int h = (i / (64 * NBLK)) % H_;
    int b = i / (64 * NBLK * H_);
    g_Kf[((size_t)((b * H_ + h) * NBLK + nb)) * QKD_ + 128 + e] = g_cmp_pe[((size_t)(b * NBLK + nb)) * 64 + e];
}

// ---------------- attention: raw-smem + split-at-read tf32, cp.async ------
// smem: sS 32x260 | sBuf 19200 floats:
//   phase1: sQ 32x196 (at 0) | sK0 32x196 (at 6400) | sK1 (at 12672)
//   phase2: sV0 64x136 (at 0) | sV1 (at 8704)
// total 27520 floats = 110080 B -> 2 CTAs/SM
#define SP  260
#define QS  196
#define KS2 196
#define VS2 136
#define ATTN_SMEM_FLOATS (32 * SP + 19200)

__global__ void __launch_bounds__(256, 2)
attn_kernel(const float* __restrict__ q, float* __restrict__ out)
{
    extern __shared__ float sm[];
    float* sS   = sm;
    float* sBuf = sm + 32 * SP;
    float* sQ   = sBuf;
    float* sK0  = sBuf + 6400;
    float* sK1  = sBuf + 12672;
    float* sV0  = sBuf;
    float* sV1  = sBuf + 8704;

    const int qt = blockIdx.x, h = blockIdx.y, b = blockIdx.z;
    const int s0 = qt * 32;
    const int t = threadIdx.x;
    const int w = t >> 5, lane = t & 31;
    const int g = lane >> 2, tig = lane & 3;
    const int mrow = 16 * (w & 1);
    const int nloc8 = (w >> 1) * 8;

    const int nmax_tile = s0 >> 4;
    const int nkt = min(8, nmax_tile / 32 + 1);   // 32-col K tiles
    const int nvt = min(4, nmax_tile / 64 + 1);   // 64-col V tiles
    const int ncols = nvt * 64;

    const float* Kb = g_Kf + (size_t)(b * H_ + h) * NBLK * QKD_;
    const float* Vb = g_Vf + (size_t)(b * H_ + h) * NBLK * VD_;

    // ---- prefetch K tile 0 ----
    for (int i = t; i < 32 * 48; i += 256) {
        int r = i / 48, c = i % 48;
        cp16(sK0 + r * KS2 + c * 4, Kb + (size_t)r * QKD_ + c * 4, r < NBLK);
    }
    CP_COMMIT();

    // ---- Q raw load ----
    const float* qb = q + ((size_t)(b * S_ + s0) * H_ + h) * QKD_;
    for (int i = t; i < 32 * 48; i += 256) {
        int r = i / 48, c = i % 48;
        float4 v = ((const float4*)(qb + (size_t)r * H_ * QKD_))[c];
        *(float4*)(sQ + r * QS + c * 4) = v;
    }

    // ---- scores: tiles of 32 columns, double buffered ----
    for (int nt = 0; nt < nkt; nt++) {
        if (nt + 1 < nkt) {
            float* dst = ((nt + 1) & 1) ? sK1 : sK0;
            int n0 = (nt + 1) * 32;
            for (int i = t; i < 32 * 48; i += 256) {
                int r = i / 48, c = i % 48;
                int n = n0 + r;
                cp16(dst + r * KS2 + c * 4, Kb + (size_t)n * QKD_ + c * 4, n < NBLK);
            }
            CP_COMMIT();
            CP_WAIT1();
        } else {
            CP_WAIT0();
        }
        __syncthreads();

        const float* sK = (nt & 1) ? sK1 : sK0;
        float acc[4] = {0.f, 0.f, 0.f, 0.f};
#pragma unroll 2
        for (int k0 = 0; k0 < 192; k0 += 8) {
            float q0 = sQ[(mrow + g) * QS + k0 + tig];
            float q1 = sQ[(mrow + g + 8) * QS + k0 + tig];
            float q2 = sQ[(mrow + g) * QS + k0 + tig + 4];
            float q3 = sQ[(mrow + g + 8) * QS + k0 + tig + 4];
            float kv0 = sK[(nloc8 + g) * KS2 + k0 + tig];
            float kv1 = sK[(nloc8 + g) * KS2 + k0 + tig + 4];
            float h0 = tf32r(q0), h1 = tf32r(q1), h2 = tf32r(q2), h3 = tf32r(q3);
            float l0 = tf32r(q0 - h0), l1 = tf32r(q1 - h1);
            float l2 = tf32r(q2 - h2), l3 = tf32r(q3 - h3);
            float bh0 = tf32r(kv0), bh1 = tf32r(kv1);
            float bl0 = tf32r(kv0 - bh0), bl1 = tf32r(kv1 - bh1);
            mma_tf32(acc, u32f(h0), u32f(h1), u32f(h2), u32f(h3), u32f(bh0), u32f(bh1));
            mma_tf32(acc, u32f(l0), u32f(l1), u32f(l2), u32f(l3), u32f(bh0), u32f(bh1));
            mma_tf32(acc, u32f(h0), u32f(h1), u32f(h2), u32f(h3), u32f(bl0), u32f(bl1));
        }
        int col = nt * 32 + nloc8 + 2 * tig;
        *(float2*)(sS + (mrow + g) * SP + col)     = make_float2(acc[0], acc[1]);
        *(float2*)(sS + (mrow + g + 8) * SP + col) = make_float2(acc[2], acc[3]);
        __syncthreads();
    }

    // ---- prefetch V tile 0 (overwrites sQ/sK0 region; safe after sync) ----
    for (int i = t; i < 64 * 32; i += 256) {
        int r = i / 32, c = i % 32;
        cp16(sV0 + r * VS2 + c * 4, Vb + (size_t)r * VD_ + c * 4, r < NBLK);
    }
    CP_COMMIT();

    // ---- softmax + p_agg in full fp32 (warp w handles rows w*4..w*4+3) ----
    const int tx = lane;
    for (int rr = 0; rr < 4; rr++) {
        int r = w * 4 + rr;
        int s = s0 + r;
        int nmax = (s >= 31) ? ((s - 31) >> 4) : -1;
        float m = -3.4e38f;
        for (int n = tx; n <= nmax; n += 32)
            m = fmaxf(m, sS[r * SP + n] * SCALE_);
#pragma unroll
        for (int o = 16; o; o >>= 1) m = fmaxf(m, __shfl_xor_sync(0xffffffffu, m, o));
        float L = 0.f;
        for (int n = tx; n < ncols; n += 32) {
            float e = 0.f;
            if (n <= nmax) e = __expf(sS[r * SP + n] * SCALE_ - m);
            sS[r * SP + n] = e;
            L += e;
        }
#pragma unroll
        for (int o = 16; o; o >>= 1) L += __shfl_xor_sync(0xffffffffu, L, o);
        if (nmax >= 0) {
            float inv = 1.f / L;
            for (int n = tx; n <= nmax; n += 32) {
                float p = sS[r * SP + n] * inv;
                sS[r * SP + n] = p;
                atomicMax((int*)&g_pagg[(size_t)(b * S_ + s) * 256 + n], __float_as_int(p));
            }
        }
    }
    __syncthreads();

    // ---- O[32x128] = P . V, tiles of 64 columns, double buffered ----
    const int nquad = w >> 1;
    float oa[4][4];
#pragma unroll
    for (int j = 0; j < 4; j++)
#pragma unroll
        for (int e = 0; e < 4; e++) oa[j][e] = 0.f;

    for (int vt = 0; vt < nvt; vt++) {
        if (vt + 1 < nvt) {
            float* dst = ((vt + 1) & 1) ? sV1 : sV0;
            int n0 = (vt + 1) * 64;
            for (int i = t; i < 64 * 32; i += 256) {
                int r = i / 32, c = i % 32;
                int n = n0 + r;
                cp16(dst + r * VS2 + c * 4, Vb + (size_t)n * VD_ + c * 4, n < NBLK);
            }
            CP_COMMIT();
            CP_WAIT1();
        } else {
            CP_WAIT0();
        }
        __syncthreads();

        const float* sV = (vt & 1) ? sV1 : sV0;
#pragma unroll 2
        for (int ks = 0; ks < 64; ks += 8) {
            int k0 = vt * 64 + ks;
            unsigned a0 = u32f(tf32r(sS[(mrow + g) * SP + k0 + tig]));
            unsigned a1 = u32f(tf32r(sS[(mrow + g + 8) * SP + k0 + tig]));
            unsigned a2 = u32f(tf32r(sS[(mrow + g) * SP + k0 + tig + 4]));
            unsigned a3 = u32f(tf32r(sS[(mrow + g + 8) * SP + k0 + tig + 4]));
#pragma unroll
            for (int j = 0; j < 4; j++) {
                const float* vb = sV + (ks + tig) * VS2 + nquad * 32 + j * 8 + g;
                unsigned b0 = u32f(tf32r(vb[0]));
                unsigned b1 = u32f(tf32r(vb[4 * VS2]));
                mma_tf32(oa[j], a0, a1, a2, a3, b0, b1);
            }
        }
        __syncthreads();
    }

    // ---- write O ----
#pragma unroll
    for (int j = 0; j < 4; j++) {
        int col = nquad * 32 + j * 8 + 2 * tig;
        {
            int s = s0 + mrow + g;
            float* orow = out + (size_t)(b * S_ + s) * (H_ * VD_) + h * VD_ + col;
            *(float2*)orow = make_float2(oa[j][0], oa[j][1]);
        }
        {
            int s = s0 + mrow + g + 8;
            float* orow = out + (size_t)(b * S_ + s) * (H_ * VD_) + h * VD_ + col;
            *(float2*)orow = make_float2(oa[j][2], oa[j][3]);
        }
    }
}

// ---------------- top-k selection ----------------
__global__ void topk_kernel(float* __restrict__ out)
{
    int idx = blockIdx.x * blockDim.x + threadIdx.x;   // b*S + s
    if (idx >= B_ * S_) return;
    int s = idx & (S_ - 1);
    int jt = s >> 6;
    const float* pa = g_pagg + (size_t)idx * 256;

    float sc[64];
#pragma unroll 1
    for (int j = 0; j < 64; j++) {
        if (j > jt)                { sc[j] = -1e9f; continue; }   // not causal
        if (j == 0 || j >= jt - 1) { sc[j] =  1e9f; continue; }   // forced
        int nlo = 4 * j - 1;                                      // j>=1 so >=3
        int nhi = min(NBLK - 1, 4 * j + 3);
        float sum = 0.f;
        for (int n = nlo; n <= nhi; n++) sum += pa[n];
        sc[j] = sum;
    }
    float* o = out + (size_t)B_ * S_ * (H_ * VD_) + (size_t)idx * TOPK_;
#pragma unroll 1
    for (int k = 0; k < TOPK_; k++) {
        float best = -3.4e38f; int bi = 0;
        for (int j = 0; j < 64; j++)
            if (sc[j] > best) { best = sc[j]; bi = j; }   // strict > keeps lowest index on tie
        o[k] = (best <= -5e8f) ? -1.f : (float)bi;
        sc[bi] = -3.4e38f;
    }
}

// ---------------- launch ----------------
extern "C" void kernel_launch(void* const* d_in, const int* in_sizes, int n_in,
                              void* d_out, int out_size)
{
    const float* q       = (const float*)d_in[0];
    const float* kv_lora = (const float*)d_in[1];
    const float* k_pe    = (const float*)d_in[2];
    const float* Wck     = (const float*)d_in[3];
    const float* Wcp     = (const float*)d_in[4];
    const float* Wkb     = (const float*)d_in[5];
    float* out = (float*)d_out;

    cudaFuncSetAttribute(attn_kernel, cudaFuncAttributeMaxDynamicSharedMemorySize,
                         ATTN_SMEM_FLOATS * (int)sizeof(float));

    // 0) zero p_agg
    {
        size_t n = (size_t)B_ * S_ * 256;
        zero_pagg_kernel<<<(unsigned)((n + 255) / 256), 256>>>();
    }
    // 1) cmp_kv split-K: M=512(510), N=512, K=16384 in 8 chunks of 2048
    gather_gemm_kernel<<<dim3(8, 8, KSPLIT), 256>>>(kv_lora, Wck, 9, 512, 2048, 0);
    // 2) cmp_pe split-K: M=512(510), N=64, K=2048 in 8 chunks of 256
    gather_gemm_kernel<<<dim3(8, 1, KSPLIT), 256>>>(k_pe, Wcp, 6, 64, 256, 1);
    // 3) reduce partials
    {
        int tot = 510 * 512 + 510 * 64;
        reduce_kernel<<<(tot + 255) / 256, 256>>>();
    }
    // 4) kvb GEMM + scatter to Kf/Vf
    kvb_gemm_kernel<<<dim3(8, 64), 256>>>(Wkb);
    // 5) rope broadcast into Kf
    {
        int tot = B_ * H_ * NBLK * ROPE_;
        rope_fill_kernel<<<(tot + 255) / 256, 256>>>();
    }
    // 6) attention (+ probs max into p_agg)
    attn_kernel<<<dim3(S_ / 32, H_, B_), 256, ATTN_SMEM_FLOATS * (int)sizeof(float)>>>(q, out);
    // 7) top-k indices
    topk_kernel<<<(B_ * S_ + 255) / 256, 256>>>(out);
}